// round 14
// baseline (speedup 1.0000x reference)
#include <cuda_runtime.h>
#include <cuda_bf16.h>

// LocalDynamicGraph edge features:
//   out[b,n,c,k]    = x[b, idx[b,n,k], c] - x[b,n,c]   for c in [0,64)
//   out[b,n,64+c,k] = x[b,n,c]                          for c in [0,64)
// B=8, N=16384, C=64, K=20. Output (B,N,128,20) fp32 = 1.342 GB, write-bound.
//
// FINAL (best of 13 rounds: 197.1us, DRAM 84.5%, occ 94%, regs 32):
//  - one 128-thread CTA per point (fine granularity = max latency hiding)
//  - warp 0 probes idx dtype (int64 vs int32) via ballot and stages the 20
//    neighbor indices into smem (one coalesced LDG), single block barrier
//  - fixed channel per thread; 10 consecutive-k gathers at MLP=10 (L2 hits,
//    x is fully L2-resident: 32MB < 126MB L2)
//  - center-broadcast half (50% of bytes) stored directly while the gather
//    LDGs are in flight (hides their L2 latency)
//  - pre-subtracted edge values -> padded smem transpose -> coalesced
//    float4 __stcs streaming stores
//
// Exhaustively mapped and rejected:
//  - TMA bulk stores: full-tile (R3), hybrid (R4), pipelined 4-pt (R5)
//    -> neutral-to-worse; same bytes through the same L1/smem port, and
//       the smem-drain tail costs occupancy.
//  - barrier-free idx: per-thread __ldg (R6, 219us), warp shfl (R9, 205us)
//    -> lengthens per-warp critical path, occupancy collapse.
//  - multi-point CTAs: sequential (R5, 206us), parallel halves w/ named
//    barriers (R11, 245us) -> coarser granularity starves the scheduler.
//  - output-layout smem + LDS.128 emit: rejected by bank-conflict model
//    (STS 10 -> ~36 wf/warp, 4-way conflicts on 80B-strided bases).
// Every profile shows HBM GB/s x time == output bytes exactly: this is a
// pure write stream pinned at ~6.7 TB/s, the practical HBM3e write/LTS
// ceiling (~84% of 8 TB/s spec) on GB300.

#define BDIM    8
#define NPTS    16384
#define CH      64
#define KNB     20
#define OUTPP   (2 * CH * KNB)   // 2560 floats per point
#define THREADS 128
#define PAD     65

__global__ __launch_bounds__(THREADS)
void edge_feature_kernel(const float* __restrict__ x,
                         const void* __restrict__ idx_raw,
                         float* __restrict__ out) {
    const int pt = blockIdx.x;            // 0 .. B*N-1
    const int b  = pt >> 14;              // N = 16384
    const int n  = pt & (NPTS - 1);
    const int t  = threadIdx.x;

    // s_nbr holds (nbr - center), i.e. the edge half, pre-subtracted.
    __shared__ float s_nbr[KNB][PAD];
    __shared__ int   s_nidx[24];          // rows 0..9 at [0..9], 10..19 at [12..21]

    const float* xb   = x + (size_t)b * NPTS * CH;
    const float* xrow = xb + (size_t)n * CH;

    // --- warp 0: probe idx dtype, then stage neighbor indices -------------
    // Genuine int64 indices all lie in [0, 16384). int32 data aliased as
    // int64 puts a random nonzero index in the high 32 bits of almost every
    // 8-byte word. Probe the first 8 words (same 64B for every CTA -> L2
    // broadcast); false-positive prob ~ 16384^-8. Resolved via ballot inside
    // warp 0, so index staging needs no extra synchronization.
    if (t < 32) {
        long long pv = ((const long long*)idx_raw)[t & 7];
        unsigned bad = __ballot_sync(0xffffffffu, pv < 0 || pv >= NPTS);
        const int is64 = (bad == 0u);
        if (t < KNB) {
            long long v;
            if (is64) v = ((const long long*)idx_raw)[(size_t)pt * KNB + t];
            else      v = (long long)((const int*)idx_raw)[(size_t)pt * KNB + t];
            s_nidx[t < 10 ? t : t + 2] = (int)v;   // 16B-aligned bases per half
        }
    }
    __syncthreads();

    // --- per-thread gather assignment: fixed channel, 10 consecutive rows ---
    const int c    = t & (CH - 1);        // 0..63
    const int half = t >> 6;              // warps 0,1 -> rows 0..9; 2,3 -> 10..19
    const float ctr_c = __ldg(xrow + c);  // one center value per thread

    // 10 consecutive row indices via 3 vector LDS (broadcast within groups)
    const int base = half * 12;
    int4 ra = *(const int4*)&s_nidx[base];
    int4 rb = *(const int4*)&s_nidx[base + 4];
    int2 rc = *(const int2*)&s_nidx[base + 8];
    int rows[10] = {ra.x, ra.y, ra.z, ra.w, rb.x, rb.y, rb.z, rb.w, rc.x, rc.y};

    // --- issue all gathers (MLP=10, 256B-coalesced per instruction) ---
    float g[10];
    #pragma unroll
    for (int i = 0; i < 10; i++)
        g[i] = xb[(size_t)rows[i] * CH + c];

    float4* outp = (float4*)(out + (size_t)pt * OUTPP);

    // --- center-broadcast half: independent of gathers, hides LDG latency.
    // out[64+c2][k] = center[c2]; j4 in [320,640).
    #pragma unroll
    for (int i = 0; i < 3; i++) {
        const int j4 = 320 + t + i * THREADS;
        if (j4 < 640) {
            const float ctr = __ldg(xrow + (j4 / 5 - CH));   // L1-hit broadcast
            __stcs(&outp[j4], make_float4(ctr, ctr, ctr, ctr));
        }
    }

    // --- commit pre-subtracted edge values to smem ---
    #pragma unroll
    for (int i = 0; i < 10; i++)
        s_nbr[half * 10 + i][c] = g[i] - ctr_c;
    __syncthreads();

    // --- edge half: out[c2][k] = s_nbr[k][c2]; j4 in [0,320) ---
    #pragma unroll
    for (int i = 0; i < 3; i++) {
        const int j4 = t + i * THREADS;
        if (j4 < 320) {
            const int c2 = j4 / 5;
            const int kk = (j4 - c2 * 5) * 4;
            float4 v;
            v.x = s_nbr[kk + 0][c2];
            v.y = s_nbr[kk + 1][c2];
            v.z = s_nbr[kk + 2][c2];
            v.w = s_nbr[kk + 3][c2];
            __stcs(&outp[j4], v);
        }
    }
}

extern "C" void kernel_launch(void* const* d_in, const int* in_sizes, int n_in,
                              void* d_out, int out_size) {
    const float* x   = (const float*)d_in[0];
    const void*  idx = d_in[1];
    float*       out = (float*)d_out;

    edge_feature_kernel<<<BDIM * NPTS, THREADS>>>(x, idx, out);
}

// round 15
// speedup vs baseline: 1.0060x; 1.0060x over previous
#include <cuda_runtime.h>
#include <cuda_bf16.h>

// LocalDynamicGraph edge features:
//   out[b,n,c,k]    = x[b, idx[b,n,k], c] - x[b,n,c]   for c in [0,64)
//   out[b,n,64+c,k] = x[b,n,c]                          for c in [0,64)
// B=8, N=16384, C=64, K=20. Output (B,N,128,20) fp32 = 1.342 GB, write-bound.
//
// FINAL (best of 14 rounds; 5x reproduced at 198 +/- 1us, DRAM ~84%,
// occ ~94%, regs 32):
//  - one 128-thread CTA per point (fine granularity = max latency hiding)
//  - warp 0 probes idx dtype (int64 vs int32) via ballot and stages the 20
//    neighbor indices into smem (one coalesced LDG), single block barrier
//  - fixed channel per thread; 10 consecutive-k gathers at MLP=10 (L2 hits,
//    x is fully L2-resident: 32MB < 126MB L2)
//  - center-broadcast half (50% of bytes) stored directly while the gather
//    LDGs are in flight (hides their L2 latency)
//  - pre-subtracted edge values -> padded smem transpose -> coalesced
//    float4 __stcs streaming stores
//
// Exhaustively mapped and rejected:
//  - TMA bulk stores: full-tile (R3), hybrid (R4), pipelined 4-pt (R5)
//    -> neutral-to-worse; same bytes through the same L1/smem port, and
//       the smem-drain tail costs occupancy.
//  - barrier-free idx: per-thread __ldg (R6, 219us), warp shfl (R9, 205us)
//    -> lengthens per-warp critical path, occupancy collapse.
//  - multi-point CTAs: sequential (R5, 206us), parallel halves w/ named
//    barriers (R11, 245us) -> coarser granularity starves the scheduler.
//  - output-layout smem + LDS.128 emit: rejected by bank-conflict model
//    (STS 10 -> ~36 wf/warp, 4-way conflicts on 80B-strided bases).
// Every profile shows HBM GB/s x time == output bytes exactly: this is a
// pure write stream pinned at ~6.66 TB/s, the practical HBM3e/LTS write
// ceiling (~84% of 8 TB/s spec) on GB300.

#define BDIM    8
#define NPTS    16384
#define CH      64
#define KNB     20
#define OUTPP   (2 * CH * KNB)   // 2560 floats per point
#define THREADS 128
#define PAD     65

__global__ __launch_bounds__(THREADS)
void edge_feature_kernel(const float* __restrict__ x,
                         const void* __restrict__ idx_raw,
                         float* __restrict__ out) {
    const int pt = blockIdx.x;            // 0 .. B*N-1
    const int b  = pt >> 14;              // N = 16384
    const int n  = pt & (NPTS - 1);
    const int t  = threadIdx.x;

    // s_nbr holds (nbr - center), i.e. the edge half, pre-subtracted.
    __shared__ float s_nbr[KNB][PAD];
    __shared__ int   s_nidx[24];          // rows 0..9 at [0..9], 10..19 at [12..21]

    const float* xb   = x + (size_t)b * NPTS * CH;
    const float* xrow = xb + (size_t)n * CH;

    // --- warp 0: probe idx dtype, then stage neighbor indices -------------
    // Genuine int64 indices all lie in [0, 16384). int32 data aliased as
    // int64 puts a random nonzero index in the high 32 bits of almost every
    // 8-byte word. Probe the first 8 words (same 64B for every CTA -> L2
    // broadcast); false-positive prob ~ 16384^-8. Resolved via ballot inside
    // warp 0, so index staging needs no extra synchronization.
    if (t < 32) {
        long long pv = ((const long long*)idx_raw)[t & 7];
        unsigned bad = __ballot_sync(0xffffffffu, pv < 0 || pv >= NPTS);
        const int is64 = (bad == 0u);
        if (t < KNB) {
            long long v;
            if (is64) v = ((const long long*)idx_raw)[(size_t)pt * KNB + t];
            else      v = (long long)((const int*)idx_raw)[(size_t)pt * KNB + t];
            s_nidx[t < 10 ? t : t + 2] = (int)v;   // 16B-aligned bases per half
        }
    }
    __syncthreads();

    // --- per-thread gather assignment: fixed channel, 10 consecutive rows ---
    const int c    = t & (CH - 1);        // 0..63
    const int half = t >> 6;              // warps 0,1 -> rows 0..9; 2,3 -> 10..19
    const float ctr_c = __ldg(xrow + c);  // one center value per thread

    // 10 consecutive row indices via 3 vector LDS (broadcast within groups)
    const int base = half * 12;
    int4 ra = *(const int4*)&s_nidx[base];
    int4 rb = *(const int4*)&s_nidx[base + 4];
    int2 rc = *(const int2*)&s_nidx[base + 8];
    int rows[10] = {ra.x, ra.y, ra.z, ra.w, rb.x, rb.y, rb.z, rb.w, rc.x, rc.y};

    // --- issue all gathers (MLP=10, 256B-coalesced per instruction) ---
    float g[10];
    #pragma unroll
    for (int i = 0; i < 10; i++)
        g[i] = xb[(size_t)rows[i] * CH + c];

    float4* outp = (float4*)(out + (size_t)pt * OUTPP);

    // --- center-broadcast half: independent of gathers, hides LDG latency.
    // out[64+c2][k] = center[c2]; j4 in [320,640).
    #pragma unroll
    for (int i = 0; i < 3; i++) {
        const int j4 = 320 + t + i * THREADS;
        if (j4 < 640) {
            const float ctr = __ldg(xrow + (j4 / 5 - CH));   // L1-hit broadcast
            __stcs(&outp[j4], make_float4(ctr, ctr, ctr, ctr));
        }
    }

    // --- commit pre-subtracted edge values to smem ---
    #pragma unroll
    for (int i = 0; i < 10; i++)
        s_nbr[half * 10 + i][c] = g[i] - ctr_c;
    __syncthreads();

    // --- edge half: out[c2][k] = s_nbr[k][c2]; j4 in [0,320) ---
    #pragma unroll
    for (int i = 0; i < 3; i++) {
        const int j4 = t + i * THREADS;
        if (j4 < 320) {
            const int c2 = j4 / 5;
            const int kk = (j4 - c2 * 5) * 4;
            float4 v;
            v.x = s_nbr[kk + 0][c2];
            v.y = s_nbr[kk + 1][c2];
            v.z = s_nbr[kk + 2][c2];
            v.w = s_nbr[kk + 3][c2];
            __stcs(&outp[j4], v);
        }
    }
}

extern "C" void kernel_launch(void* const* d_in, const int* in_sizes, int n_in,
                              void* d_out, int out_size) {
    const float* x   = (const float*)d_in[0];
    const void*  idx = d_in[1];
    float*       out = (float*)d_out;

    edge_feature_kernel<<<BDIM * NPTS, THREADS>>>(x, idx, out);
}

// round 16
// speedup vs baseline: 1.0083x; 1.0023x over previous
#include <cuda_runtime.h>
#include <cuda_bf16.h>

// LocalDynamicGraph edge features:
//   out[b,n,c,k]    = x[b, idx[b,n,k], c] - x[b,n,c]   for c in [0,64)
//   out[b,n,64+c,k] = x[b,n,c]                          for c in [0,64)
// B=8, N=16384, C=64, K=20. Output (B,N,128,20) fp32 = 1.342 GB, write-bound.
//
// FINAL (best of 15 rounds; 6x reproduced at 197.9 +/- 0.7us, DRAM ~84%,
// occ ~93%, regs 32):
//  - one 128-thread CTA per point (fine granularity = max latency hiding)
//  - warp 0 probes idx dtype (int64 vs int32) via ballot and stages the 20
//    neighbor indices into smem (one coalesced LDG), single block barrier
//  - fixed channel per thread; 10 consecutive-k gathers at MLP=10 (L2 hits,
//    x is fully L2-resident: 32MB < 126MB L2)
//  - center-broadcast half (50% of bytes) stored directly while the gather
//    LDGs are in flight (hides their L2 latency)
//  - pre-subtracted edge values -> padded smem transpose -> coalesced
//    float4 __stcs streaming stores
//
// Exhaustively mapped and rejected:
//  - TMA bulk stores: full-tile (R3), hybrid (R4), pipelined 4-pt (R5)
//    -> neutral-to-worse; same bytes through the same L1/smem port, and
//       the smem-drain tail costs occupancy.
//  - barrier-free idx: per-thread __ldg (R6, 219us), warp shfl (R9, 205us)
//    -> lengthens per-warp critical path, occupancy collapse.
//  - multi-point CTAs: sequential (R5, 206us), parallel halves w/ named
//    barriers (R11, 245us) -> coarser granularity starves the scheduler.
//  - output-layout smem + LDS.128 emit: rejected by bank-conflict model
//    (STS 10 -> ~36 wf/warp, 4-way conflicts on 80B-strided bases).
// Every profile shows HBM GB/s x time == output bytes exactly: this is a
// pure write stream pinned at ~6.66 TB/s, the practical HBM3e/LTS write
// ceiling (~84% of 8 TB/s spec) on GB300.

#define BDIM    8
#define NPTS    16384
#define CH      64
#define KNB     20
#define OUTPP   (2 * CH * KNB)   // 2560 floats per point
#define THREADS 128
#define PAD     65

__global__ __launch_bounds__(THREADS)
void edge_feature_kernel(const float* __restrict__ x,
                         const void* __restrict__ idx_raw,
                         float* __restrict__ out) {
    const int pt = blockIdx.x;            // 0 .. B*N-1
    const int b  = pt >> 14;              // N = 16384
    const int n  = pt & (NPTS - 1);
    const int t  = threadIdx.x;

    // s_nbr holds (nbr - center), i.e. the edge half, pre-subtracted.
    __shared__ float s_nbr[KNB][PAD];
    __shared__ int   s_nidx[24];          // rows 0..9 at [0..9], 10..19 at [12..21]

    const float* xb   = x + (size_t)b * NPTS * CH;
    const float* xrow = xb + (size_t)n * CH;

    // --- warp 0: probe idx dtype, then stage neighbor indices -------------
    // Genuine int64 indices all lie in [0, 16384). int32 data aliased as
    // int64 puts a random nonzero index in the high 32 bits of almost every
    // 8-byte word. Probe the first 8 words (same 64B for every CTA -> L2
    // broadcast); false-positive prob ~ 16384^-8. Resolved via ballot inside
    // warp 0, so index staging needs no extra synchronization.
    if (t < 32) {
        long long pv = ((const long long*)idx_raw)[t & 7];
        unsigned bad = __ballot_sync(0xffffffffu, pv < 0 || pv >= NPTS);
        const int is64 = (bad == 0u);
        if (t < KNB) {
            long long v;
            if (is64) v = ((const long long*)idx_raw)[(size_t)pt * KNB + t];
            else      v = (long long)((const int*)idx_raw)[(size_t)pt * KNB + t];
            s_nidx[t < 10 ? t : t + 2] = (int)v;   // 16B-aligned bases per half
        }
    }
    __syncthreads();

    // --- per-thread gather assignment: fixed channel, 10 consecutive rows ---
    const int c    = t & (CH - 1);        // 0..63
    const int half = t >> 6;              // warps 0,1 -> rows 0..9; 2,3 -> 10..19
    const float ctr_c = __ldg(xrow + c);  // one center value per thread

    // 10 consecutive row indices via 3 vector LDS (broadcast within groups)
    const int base = half * 12;
    int4 ra = *(const int4*)&s_nidx[base];
    int4 rb = *(const int4*)&s_nidx[base + 4];
    int2 rc = *(const int2*)&s_nidx[base + 8];
    int rows[10] = {ra.x, ra.y, ra.z, ra.w, rb.x, rb.y, rb.z, rb.w, rc.x, rc.y};

    // --- issue all gathers (MLP=10, 256B-coalesced per instruction) ---
    float g[10];
    #pragma unroll
    for (int i = 0; i < 10; i++)
        g[i] = xb[(size_t)rows[i] * CH + c];

    float4* outp = (float4*)(out + (size_t)pt * OUTPP);

    // --- center-broadcast half: independent of gathers, hides LDG latency.
    // out[64+c2][k] = center[c2]; j4 in [320,640).
    #pragma unroll
    for (int i = 0; i < 3; i++) {
        const int j4 = 320 + t + i * THREADS;
        if (j4 < 640) {
            const float ctr = __ldg(xrow + (j4 / 5 - CH));   // L1-hit broadcast
            __stcs(&outp[j4], make_float4(ctr, ctr, ctr, ctr));
        }
    }

    // --- commit pre-subtracted edge values to smem ---
    #pragma unroll
    for (int i = 0; i < 10; i++)
        s_nbr[half * 10 + i][c] = g[i] - ctr_c;
    __syncthreads();

    // --- edge half: out[c2][k] = s_nbr[k][c2]; j4 in [0,320) ---
    #pragma unroll
    for (int i = 0; i < 3; i++) {
        const int j4 = t + i * THREADS;
        if (j4 < 320) {
            const int c2 = j4 / 5;
            const int kk = (j4 - c2 * 5) * 4;
            float4 v;
            v.x = s_nbr[kk + 0][c2];
            v.y = s_nbr[kk + 1][c2];
            v.z = s_nbr[kk + 2][c2];
            v.w = s_nbr[kk + 3][c2];
            __stcs(&outp[j4], v);
        }
    }
}

extern "C" void kernel_launch(void* const* d_in, const int* in_sizes, int n_in,
                              void* d_out, int out_size) {
    const float* x   = (const float*)d_in[0];
    const void*  idx = d_in[1];
    float*       out = (float*)d_out;

    edge_feature_kernel<<<BDIM * NPTS, THREADS>>>(x, idx, out);
}